// round 1
// baseline (speedup 1.0000x reference)
#include <cuda_runtime.h>
#include <math.h>

// Problem: B=64, T=1024, D=512, H=512
//   xw = x @ W[:512] + b          (65536x512x512 GEMM)
//   h_t = tanh(xw_t + h_{t-1} @ W[512:])   scan over T
//
// Phase 1: FFMA2 (packed f32x2) tiled GEMM -> g_xw scratch
// Phase 2: persistent kernel, 128 blocks, Wh held in registers,
//          software grid barrier per timestep.

#define NBLK 128

__device__ float g_xw[64u * 1024u * 512u];      // 128 MB scratch: [b][t][h]
__device__ float g_h[2][512 * 64];              // ping-pong h, [feature][batch]
__device__ unsigned int g_bar_gen;
__device__ unsigned int g_bar_cnt;

#define FMA2(d, a, b, c) \
    asm("fma.rn.f32x2 %0, %1, %2, %3;" : "=l"(d) : "l"(a), "l"(b), "l"(c))
#define PACK2(d, lo, hi) \
    asm("mov.b64 %0, {%1, %2};" : "=l"(d) : "f"(lo), "f"(hi))
#define UNPACK2(lo, hi, v) \
    asm("mov.b64 {%0, %1}, %2;" : "=f"(lo), "=f"(hi) : "l"(v))

// ---------------------------------------------------------------------------
// Phase 1: g_xw[m][n] = sum_k x[m][k] * W[k][n] + b[n],  m in [0,65536)
// Block tile 128x128, K-tile 16, 256 threads, 8x8 micro-tile via f32x2.
// ---------------------------------------------------------------------------
__global__ __launch_bounds__(256) void xw_gemm(const float* __restrict__ x,
                                               const float* __restrict__ W,
                                               const float* __restrict__ bias) {
    __shared__ __align__(16) float Ast[16][132];  // [k][m] transposed, padded
    __shared__ __align__(16) float Bs[16][128];   // [k][n]

    const int tid = threadIdx.x;
    const int bn = blockIdx.x & 3;       // 4 col-blocks  (512/128)
    const int bm = blockIdx.x >> 2;      // 512 row-blocks (65536/128)
    const int row0 = bm << 7;
    const int n0 = bn << 7;
    const int mt = tid >> 4;             // 0..15
    const int nt = tid & 15;             // 0..15

    unsigned long long acc[4][8];
#pragma unroll
    for (int p = 0; p < 4; p++)
#pragma unroll
        for (int j = 0; j < 8; j++) acc[p][j] = 0ULL;

    for (int kt = 0; kt < 512; kt += 16) {
        // load A tile (128 rows x 16 k), store transposed
#pragma unroll
        for (int it = 0; it < 2; it++) {
            int idx = tid + (it << 8);
            int m = idx >> 2;
            int kq = (idx & 3) << 2;
            float4 v = *(const float4*)(x + (size_t)(row0 + m) * 512 + kt + kq);
            Ast[kq + 0][m] = v.x;
            Ast[kq + 1][m] = v.y;
            Ast[kq + 2][m] = v.z;
            Ast[kq + 3][m] = v.w;
        }
        // load B tile (16 k x 128 n)
#pragma unroll
        for (int it = 0; it < 2; it++) {
            int idx = tid + (it << 8);
            int k = idx >> 5;
            int nq = (idx & 31) << 2;
            *(float4*)(&Bs[k][nq]) =
                *(const float4*)(W + (size_t)(kt + k) * 512 + n0 + nq);
        }
        __syncthreads();
#pragma unroll
        for (int k = 0; k < 16; k++) {
            // rows: 4*mt..4*mt+3 and 64+4*mt..64+4*mt+3 (as f32x2 pairs)
            ulonglong2 aA = *(const ulonglong2*)(&Ast[k][4 * mt]);
            ulonglong2 aB = *(const ulonglong2*)(&Ast[k][64 + 4 * mt]);
            // cols: 4*nt..4*nt+3 and 64+4*nt..64+4*nt+3
            float4 b0 = *(const float4*)(&Bs[k][4 * nt]);
            float4 b1 = *(const float4*)(&Bs[k][64 + 4 * nt]);
            unsigned long long bb[8];
            PACK2(bb[0], b0.x, b0.x);
            PACK2(bb[1], b0.y, b0.y);
            PACK2(bb[2], b0.z, b0.z);
            PACK2(bb[3], b0.w, b0.w);
            PACK2(bb[4], b1.x, b1.x);
            PACK2(bb[5], b1.y, b1.y);
            PACK2(bb[6], b1.z, b1.z);
            PACK2(bb[7], b1.w, b1.w);
#pragma unroll
            for (int j = 0; j < 8; j++) {
                FMA2(acc[0][j], aA.x, bb[j], acc[0][j]);
                FMA2(acc[1][j], aA.y, bb[j], acc[1][j]);
                FMA2(acc[2][j], aB.x, bb[j], acc[2][j]);
                FMA2(acc[3][j], aB.y, bb[j], acc[3][j]);
            }
        }
        __syncthreads();
    }

    // epilogue: unpack, add bias, store to g_xw
    float bv[8];
#pragma unroll
    for (int j = 0; j < 4; j++) {
        bv[j] = bias[n0 + 4 * nt + j];
        bv[4 + j] = bias[n0 + 64 + 4 * nt + j];
    }
    float res[8][8];
#pragma unroll
    for (int p = 0; p < 4; p++)
#pragma unroll
        for (int j = 0; j < 8; j++) {
            float lo, hi;
            UNPACK2(lo, hi, acc[p][j]);
            res[2 * p][j] = lo + bv[j];
            res[2 * p + 1][j] = hi + bv[j];
        }
#pragma unroll
    for (int rI = 0; rI < 8; rI++) {
        int lrow = (rI < 4) ? (4 * mt + rI) : (64 + 4 * mt + (rI - 4));
        size_t base = (size_t)(row0 + lrow) * 512 + n0;
        float4 s0 = make_float4(res[rI][0], res[rI][1], res[rI][2], res[rI][3]);
        float4 s1 = make_float4(res[rI][4], res[rI][5], res[rI][6], res[rI][7]);
        *(float4*)(g_xw + base + 4 * nt) = s0;
        *(float4*)(g_xw + base + 64 + 4 * nt) = s1;
    }
}

// ---------------------------------------------------------------------------
__global__ void init_bar() {
    g_bar_gen = 0u;
    g_bar_cnt = 0u;
}

// ---------------------------------------------------------------------------
// Phase 2: persistent scan. 128 blocks, each owns an 8-row x 32-col tile of
// h_new. Wh slice lives in registers (64 floats/thread). Per step:
//   load h slab -> smem (broadcast reads) -> f32x2 partial dots ->
//   smem reduction over k-chunks -> +xw -> tanh -> store out + h ping-pong ->
//   software grid barrier.
// ---------------------------------------------------------------------------
__global__ __launch_bounds__(256, 1) void rnn_scan(const float* __restrict__ W,
                                                   float* __restrict__ out) {
    const int bid = blockIdx.x;
    const int r0 = (bid >> 4) << 3;    // 8 row-groups of 8 batch rows
    const int c0 = (bid & 15) << 5;    // 16 col-groups of 32 features
    const int tid = threadIdx.x;
    const int c = tid & 31;            // feature within tile
    const int ks = tid >> 5;           // k-chunk 0..7 (64 k each)

    __shared__ __align__(16) float hst[512 * 8];  // [k][r] slab, 16 KB
    __shared__ float red[8][8][33];               // [kchunk][r][c]

    // Wh slice into registers: wreg[j] = W[512 + ks*64 + j][c0 + c]
    float wreg[64];
#pragma unroll
    for (int j = 0; j < 64; j++) {
        int k = (ks << 6) + j;
        wreg[j] = W[(size_t)(512 + k) * 512 + c0 + c];
    }

    const int rr = tid >> 5;  // epilogue row 0..7
    const int cc = tid & 31;  // epilogue col 0..31

    for (int t = 0; t < 1024; t++) {
        // prefetch xw for this (row, t, col) — consumed after the reduction
        float xwv = g_xw[((size_t)(r0 + rr) * 1024 + (size_t)t) * 512 + c0 + cc];

        unsigned long long acc0 = 0ULL, acc1 = 0ULL, acc2 = 0ULL, acc3 = 0ULL;
        if (t > 0) {
            const float* hcur = g_h[t & 1];
            // fill h slab: hst[k*8 + r] = h[r0+r][k]
            for (int i = tid; i < 4096; i += 256) {
                hst[i] = hcur[((i >> 3) << 6) + r0 + (i & 7)];
            }
            __syncthreads();
#pragma unroll
            for (int j = 0; j < 64; j++) {
                int k = (ks << 6) + j;
                ulonglong2 hA = *(const ulonglong2*)(&hst[k * 8]);      // rows 0-3
                ulonglong2 hB = *(const ulonglong2*)(&hst[k * 8 + 4]);  // rows 4-7
                unsigned long long w2;
                PACK2(w2, wreg[j], wreg[j]);
                FMA2(acc0, hA.x, w2, acc0);
                FMA2(acc1, hA.y, w2, acc1);
                FMA2(acc2, hB.x, w2, acc2);
                FMA2(acc3, hB.y, w2, acc3);
            }
        }
        // partials -> smem
        float p0, p1;
        UNPACK2(p0, p1, acc0); red[ks][0][c] = p0; red[ks][1][c] = p1;
        UNPACK2(p0, p1, acc1); red[ks][2][c] = p0; red[ks][3][c] = p1;
        UNPACK2(p0, p1, acc2); red[ks][4][c] = p0; red[ks][5][c] = p1;
        UNPACK2(p0, p1, acc3); red[ks][6][c] = p0; red[ks][7][c] = p1;
        __syncthreads();

        // reduce over 8 k-chunks, + xw, tanh
        float s = xwv;
#pragma unroll
        for (int q = 0; q < 8; q++) s += red[q][rr][cc];
        float v = tanhf(s);

        out[((size_t)(r0 + rr) * 1024 + (size_t)t) * 512 + c0 + cc] = v;

        if (t < 1023) {
            g_h[(t + 1) & 1][(size_t)(c0 + cc) * 64 + r0 + rr] = v;

            // ---- software grid barrier (sense = generation counter) ----
            __syncthreads();
            if (tid == 0) {
                __threadfence();
                unsigned int a = atomicAdd(&g_bar_cnt, 1u);
                if (a == NBLK - 1) {
                    g_bar_cnt = 0u;
                    __threadfence();
                    atomicAdd(&g_bar_gen, 1u);
                } else {
                    const unsigned int target = (unsigned int)(t + 1);
                    unsigned int g;
                    do {
                        asm volatile("ld.acquire.gpu.u32 %0, [%1];"
                                     : "=r"(g)
                                     : "l"(&g_bar_gen)
                                     : "memory");
                    } while (g < target);
                }
                __threadfence();
            }
            __syncthreads();
        }
    }
}

// ---------------------------------------------------------------------------
extern "C" void kernel_launch(void* const* d_in, const int* in_sizes, int n_in,
                              void* d_out, int out_size) {
    const float* x = (const float*)d_in[0];    // (64, 1024, 512) f32
    const float* W = (const float*)d_in[1];    // (1024, 512) f32
    const float* b = (const float*)d_in[2];    // (512,) f32
    float* out = (float*)d_out;                // (64, 1024, 512) f32

    xw_gemm<<<2048, 256>>>(x, W, b);
    init_bar<<<1, 1>>>();
    rnn_scan<<<NBLK, 256>>>(W, out);
}